// round 3
// baseline (speedup 1.0000x reference)
#include <cuda_runtime.h>
#include <math.h>

#define B_    16
#define H_    512
#define W_    512
#define NPIX  (B_ * H_ * W_)
#define BIGF  100000000.0f
#define MAIN_BLOCKS_X 64
#define MAIN_TOTAL (MAIN_BLOCKS_X * B_)

// ---------------- scratch (device globals; no allocation) ----------------
__device__ unsigned short g_d[NPIX];       // vertical distance dmin (0..511, 0x7FFF = BIG)
__device__ float  g_rowsf[B_ * W_];        // f at h==b rows (squared)
__device__ int    g_maxf[B_];              // per-batch max of f (float bits, f>=0)
__device__ double g_acc[4];                // [wmse_sum, sum_p, sum_t, sum_pt]
__device__ unsigned int g_done;            // grid-completion counter for k_main

// ================= K1: vertical distance via bitmask chunks =================
// Block: 512 threads = 64 columns x 8 chunks of 64 rows. Grid: (W/64, B) = (8,16).
__global__ void k_vert(const float* __restrict__ t) {
    __shared__ int s_last[8][64];
    __shared__ int s_first[8][64];

    const int c_tile = blockIdx.x;
    const int b      = blockIdx.y;
    const int c      = threadIdx.x & 63;
    const int k      = threadIdx.x >> 6;
    const int col    = c_tile * 64 + c;
    const int r0     = k * 64;

    // zero accumulators once per launch (consumed only by later kernels)
    if (blockIdx.x == 0 && blockIdx.y == 0) {
        if (threadIdx.x < B_) g_maxf[threadIdx.x] = 0;
        if (threadIdx.x < 4)  g_acc[threadIdx.x]  = 0.0;
        if (threadIdx.x == 31) g_done = 0u;
    }

    const float* tb = t + (size_t)b * H_ * W_ + col;
    unsigned short* gb = g_d + (size_t)b * H_ * W_ + col;

    unsigned long long zbits = 0ull;
    #pragma unroll
    for (int i = 0; i < 64; ++i) {
        float z = tb[(size_t)(r0 + i) * W_];
        if (z == 0.0f) zbits |= (1ull << i);
    }

    const int SENT = 1 << 28;
    s_last[k][c]  = zbits ? (r0 + 63 - __clzll(zbits)) : -SENT;
    s_first[k][c] = zbits ? (r0 + __ffsll(zbits) - 1)  :  SENT;
    __syncthreads();

    int lastAbove = -SENT;
    #pragma unroll
    for (int kk = 0; kk < 8; ++kk)
        if (kk < k) lastAbove = max(lastAbove, s_last[kk][c]);
    int nextBelow = SENT;
    #pragma unroll
    for (int kk = 0; kk < 8; ++kk)
        if (kk > k) nextBelow = min(nextBelow, s_first[kk][c]);

    #pragma unroll
    for (int i = 0; i < 64; ++i) {
        int r = r0 + i;
        unsigned long long below = zbits & ((i == 63) ? ~0ull : ((2ull << i) - 1ull));
        int lz = below ? (r0 + 63 - __clzll(below)) : lastAbove;
        unsigned long long above = zbits >> i;
        int nz = above ? (r + __ffsll(above) - 1) : nextBelow;
        int dmin = min(r - lz, nz - r);
        gb[(size_t)r * W_] = (unsigned short)min(dmin, 0x7FFF);
    }
}

// ================= K2: row transform, 2 rows per block =================
// grid = B_*H_/2 blocks, 1024 threads (two 512-thread row groups).
__global__ void k_row() {
    __shared__ float srow[2][W_];
    __shared__ float smax[32];

    const int half = threadIdx.x >> 9;         // 0 or 1
    const int y    = threadIdx.x & 511;
    const int bh   = blockIdx.x * 2 + half;    // global row id
    const int b    = bh >> 9;
    const int h    = bh & 511;

    const unsigned short* grow = g_d + (size_t)bh * W_;
    {
        unsigned short dm = grow[y];
        srow[half][y] = (dm > 511) ? BIGF : (float)((int)dm * (int)dm);
    }
    __syncthreads();

    const float* sr = srow[half];
    float best = sr[y];
    for (int r = 1; r < W_; ++r) {
        float r2 = (float)(r * r);
        if (r2 >= best) break;                 // exact early termination
        int jl = y - r, jr = y + r;
        if (jl >= 0)  best = fminf(best, sr[jl] + r2);
        if (jr < W_)  best = fminf(best, sr[jr] + r2);
    }

    if (h == b) g_rowsf[b * W_ + y] = best;

    // block max reduce (both halves share g_maxf target only if same b; reduce per warp then atomic per half)
    float m = best;
    #pragma unroll
    for (int o = 16; o > 0; o >>= 1)
        m = fmaxf(m, __shfl_down_sync(0xffffffffu, m, o));
    if ((threadIdx.x & 31) == 0) smax[threadIdx.x >> 5] = m;
    __syncthreads();
    // warps 0..15 belong to half 0, 16..31 to half 1; lane-level final reduce
    if (threadIdx.x < 32) {
        m = smax[threadIdx.x];
        int myhalf = threadIdx.x >> 4;
        #pragma unroll
        for (int o = 8; o > 0; o >>= 1)
            m = fmaxf(m, __shfl_down_sync(0xffffffffu, m, o));
        if ((threadIdx.x & 15) == 0) {
            int bb = (blockIdx.x * 2 + myhalf) >> 9;
            atomicMax(&g_maxf[bb], __float_as_int(m));
        }
    }
}

// ================= K3: fused weighted MSE + dice + finalize =================
// grid (MAIN_BLOCKS_X, B), block 256; 4 float4 per thread.
__global__ void k_main(const float4* __restrict__ in4, const float4* __restrict__ tg4,
                       float* __restrict__ out, int out_size) {
    __shared__ float s_wb[W_];
    __shared__ float red[4][8];
    __shared__ bool s_last;

    const int b = blockIdx.y;
    const float v = sqrtf(__int_as_float(g_maxf[b]));
    {
        int t0 = threadIdx.x;
        s_wb[t0]       = v - sqrtf(g_rowsf[b * W_ + t0]);
        s_wb[t0 + 256] = v - sqrtf(g_rowsf[b * W_ + t0 + 256]);
    }
    __syncthreads();

    const size_t base4 = (size_t)b * (H_ * W_ / 4);
    const int q0 = blockIdx.x * 256 + threadIdx.x;
    const float4* wb4 = (const float4*)s_wb;

    float sw = 0.f, sp = 0.f, st = 0.f, spt = 0.f;
    #pragma unroll
    for (int k = 0; k < 4; ++k) {
        int fi = q0 + k * (MAIN_BLOCKS_X * 256);
        float4 x = in4[base4 + fi];
        float4 t = tg4[base4 + fi];
        float4 wb = wb4[fi & 127];

        float px, wgt, d;
        d = x.x - t.x; wgt = ((t.x != 0.f) ? wb.x : 0.f) + 0.001f; sw += wgt * d * d;
        px = 1.f / (1.f + __expf(-x.x)); sp += px; st += t.x; spt += px * t.x;
        d = x.y - t.y; wgt = ((t.y != 0.f) ? wb.y : 0.f) + 0.001f; sw += wgt * d * d;
        px = 1.f / (1.f + __expf(-x.y)); sp += px; st += t.y; spt += px * t.y;
        d = x.z - t.z; wgt = ((t.z != 0.f) ? wb.z : 0.f) + 0.001f; sw += wgt * d * d;
        px = 1.f / (1.f + __expf(-x.z)); sp += px; st += t.z; spt += px * t.z;
        d = x.w - t.w; wgt = ((t.w != 0.f) ? wb.w : 0.f) + 0.001f; sw += wgt * d * d;
        px = 1.f / (1.f + __expf(-x.w)); sp += px; st += t.w; spt += px * t.w;
    }

    float vals[4] = {sw, sp, st, spt};
    #pragma unroll
    for (int q = 0; q < 4; ++q) {
        float s = vals[q];
        #pragma unroll
        for (int o = 16; o > 0; o >>= 1)
            s += __shfl_down_sync(0xffffffffu, s, o);
        if ((threadIdx.x & 31) == 0) red[q][threadIdx.x >> 5] = s;
    }
    __syncthreads();
    if (threadIdx.x < 8) {
        #pragma unroll
        for (int q = 0; q < 4; ++q) {
            float s = red[q][threadIdx.x];
            #pragma unroll
            for (int o = 4; o > 0; o >>= 1)
                s += __shfl_down_sync(0xffu, s, o);
            if (threadIdx.x == 0)
                atomicAdd(&g_acc[q], (double)s);
        }
    }
    __syncthreads();

    // grid-completion: last block finalizes
    if (threadIdx.x == 0) {
        __threadfence();
        unsigned n = atomicAdd(&g_done, 1u);
        s_last = (n == MAIN_TOTAL - 1);
    }
    __syncthreads();
    if (s_last && threadIdx.x == 0) {
        double wmse = g_acc[0] / (double)NPIX;
        double P = g_acc[1], T = g_acc[2], I = g_acc[3];
        double dice = 1.0 - (2.0 * I + 1e-6) / (P + T + 1e-6);
        if (out_size >= 1) out[0] = (float)(0.6 * wmse);
        if (out_size >= 2) out[1] = (float)(1.0 * dice);
    }
}

// ---------------- launch ----------------
extern "C" void kernel_launch(void* const* d_in, const int* in_sizes, int n_in,
                              void* d_out, int out_size) {
    const float* inputs  = (const float*)d_in[0];
    const float* targets = (const float*)d_in[1];
    float* out = (float*)d_out;

    dim3 gv(W_ / 64, B_);
    k_vert<<<gv, 512>>>(targets);
    k_row<<<B_ * H_ / 2, 1024>>>();
    dim3 g3(MAIN_BLOCKS_X, B_);
    k_main<<<g3, 256>>>((const float4*)inputs, (const float4*)targets, out, out_size);
}

// round 4
// speedup vs baseline: 1.0349x; 1.0349x over previous
#include <cuda_runtime.h>
#include <math.h>

#define B_    16
#define H_    512
#define W_    512
#define NPIX  (B_ * H_ * W_)
#define BIGF  100000000.0f
#define SENTI (1 << 28)
#define MAIN_BLOCKS_X 64
#define MAIN_TOTAL (MAIN_BLOCKS_X * B_)

// ---------------- scratch (device globals; no allocation) ----------------
__device__ unsigned short g_d[NPIX];           // vertical distance (0..511, clamp 0x7FFF = BIG)
__device__ unsigned int   g_zmask[NPIX / 32];  // row-major: bit j => target==0 at pixel (word*32+j)
__device__ float  g_rowsf[B_ * W_];            // f at h==b rows (squared)
__device__ int    g_maxf[B_];                  // per-batch max of f (float bits)
__device__ double g_acc[4];                    // [wmse_sum, sum_p, sum_t, sum_pt]
__device__ unsigned int g_done;

// ================= K1: vertical distance + row-major zero mask =================
// grid (W/32, B) = (16,16), block 512 = 16 warps; warp w: rows [32w,32w+32), cols lane.
__global__ void k_vert(const float* __restrict__ t) {
    __shared__ int s_last[16][32];
    __shared__ int s_first[16][32];

    const int lane = threadIdx.x & 31;
    const int w    = threadIdx.x >> 5;       // row-chunk 0..15
    const int cg   = blockIdx.x;             // column group (32 cols)
    const int b    = blockIdx.y;
    const int col  = cg * 32 + lane;
    const int r0   = w * 32;

    if (blockIdx.x == 0 && blockIdx.y == 0) {
        if (threadIdx.x < B_) g_maxf[threadIdx.x] = 0;
        if (threadIdx.x < 4)  g_acc[threadIdx.x]  = 0.0;
        if (threadIdx.x == 31) g_done = 0u;
    }

    const float* tb = t + (size_t)b * H_ * W_;

    // load 32 rows; ballot gives row-major zero masks AND builds the column mask
    unsigned colmask = 0u, myrow = 0u;
    #pragma unroll
    for (int i = 0; i < 32; ++i) {
        float z = tb[(size_t)(r0 + i) * W_ + col];
        unsigned m = __ballot_sync(0xffffffffu, z == 0.0f);
        if (lane == i) myrow = m;
        colmask |= ((m >> lane) & 1u) << i;
    }
    // row-major zero mask: lane stores the mask of row r0+lane for this col-group
    g_zmask[((size_t)b * H_ + r0 + lane) * (W_ / 32) + cg] = myrow;

    s_last[w][lane]  = colmask ? (r0 + 31 - __clz(colmask)) : -SENTI;
    s_first[w][lane] = colmask ? (r0 + __ffs(colmask) - 1)  :  SENTI;
    __syncthreads();

    int lastAbove = -SENTI, nextBelow = SENTI;
    #pragma unroll
    for (int k = 0; k < 16; ++k) {
        int fl = s_first[k][lane];
        int ll = s_last[k][lane];
        if (k < w) lastAbove = max(lastAbove, ll);
        if (k > w) nextBelow = min(nextBelow, fl);
    }

    // incremental backward (down) distances
    int dn[32];
    int d = nextBelow - (r0 + 32);
    #pragma unroll
    for (int i = 31; i >= 0; --i) {
        d = ((colmask >> i) & 1u) ? 0 : d + 1;
        dn[i] = d;
    }
    // incremental forward (up) distances + emit
    unsigned short* gb = g_d + (size_t)b * H_ * W_ + col;
    int du = (r0 - 1) - lastAbove;
    #pragma unroll
    for (int i = 0; i < 32; ++i) {
        du = ((colmask >> i) & 1u) ? 0 : du + 1;
        int dm = min(du, dn[i]);
        gb[(size_t)(r0 + i) * W_] = (unsigned short)min(dm, 0x7FFF);
    }
}

// ================= K2: row transform, 2 rows per block =================
__global__ void k_row() {
    __shared__ float srow[2][W_];
    __shared__ float smax[32];

    const int half = threadIdx.x >> 9;
    const int y    = threadIdx.x & 511;
    const int bh   = blockIdx.x * 2 + half;
    const int b    = bh >> 9;
    const int h    = bh & 511;

    const unsigned short* grow = g_d + (size_t)bh * W_;
    {
        unsigned short dm = grow[y];
        srow[half][y] = (dm > 511) ? BIGF : (float)((int)dm * (int)dm);
    }
    __syncthreads();

    const float* sr = srow[half];
    float best = sr[y];
    for (int r = 1; r < W_; ++r) {
        float r2 = (float)(r * r);
        if (r2 >= best) break;                 // exact early termination
        int jl = y - r, jr = y + r;
        if (jl >= 0)  best = fminf(best, sr[jl] + r2);
        if (jr < W_)  best = fminf(best, sr[jr] + r2);
    }

    if (h == b) g_rowsf[b * W_ + y] = best;

    float m = best;
    #pragma unroll
    for (int o = 16; o > 0; o >>= 1)
        m = fmaxf(m, __shfl_down_sync(0xffffffffu, m, o));
    if ((threadIdx.x & 31) == 0) smax[threadIdx.x >> 5] = m;
    __syncthreads();
    if (threadIdx.x < 32) {
        m = smax[threadIdx.x];
        int myhalf = threadIdx.x >> 4;
        #pragma unroll
        for (int o = 8; o > 0; o >>= 1)
            m = fmaxf(m, __shfl_down_sync(0xffffffffu, m, o));
        if ((threadIdx.x & 15) == 0) {
            int bb = (blockIdx.x * 2 + myhalf) >> 9;
            atomicMax(&g_maxf[bb], __float_as_int(m));
        }
    }
}

// ================= K3: fused weighted MSE + dice + finalize =================
// grid (MAIN_BLOCKS_X, B), block 256; 4 float4 per thread. Targets from bitmask.
__global__ void k_main(const float4* __restrict__ in4,
                       float* __restrict__ out, int out_size) {
    __shared__ float s_wb[W_];
    __shared__ float red[4][8];
    __shared__ bool s_last;

    const int b = blockIdx.y;
    const float v = sqrtf(__int_as_float(g_maxf[b]));
    {
        int t0 = threadIdx.x;
        s_wb[t0]       = v - sqrtf(g_rowsf[b * W_ + t0]);
        s_wb[t0 + 256] = v - sqrtf(g_rowsf[b * W_ + t0 + 256]);
    }
    __syncthreads();

    const size_t base4 = (size_t)b * (H_ * W_ / 4);
    const size_t basew = (size_t)b * (H_ * W_ / 32);
    const int q0 = blockIdx.x * 256 + threadIdx.x;
    const float4* wb4 = (const float4*)s_wb;

    float sw = 0.f, sp = 0.f, st = 0.f, spt = 0.f;
    #pragma unroll
    for (int k = 0; k < 4; ++k) {
        int fi = q0 + k * (MAIN_BLOCKS_X * 256);
        float4 x = in4[base4 + fi];
        unsigned nib = (g_zmask[basew + (fi >> 3)] >> ((fi & 7) * 4)) & 0xFu;
        float4 wb = wb4[fi & 127];

        float px, wgt, dd, tt;
        tt = (nib & 1u) ? 0.f : 1.f;
        dd = x.x - tt; wgt = ((nib & 1u) ? 0.f : wb.x) + 0.001f; sw += wgt * dd * dd;
        px = 1.f / (1.f + __expf(-x.x)); sp += px; st += tt; spt += px * tt;
        tt = (nib & 2u) ? 0.f : 1.f;
        dd = x.y - tt; wgt = ((nib & 2u) ? 0.f : wb.y) + 0.001f; sw += wgt * dd * dd;
        px = 1.f / (1.f + __expf(-x.y)); sp += px; st += tt; spt += px * tt;
        tt = (nib & 4u) ? 0.f : 1.f;
        dd = x.z - tt; wgt = ((nib & 4u) ? 0.f : wb.z) + 0.001f; sw += wgt * dd * dd;
        px = 1.f / (1.f + __expf(-x.z)); sp += px; st += tt; spt += px * tt;
        tt = (nib & 8u) ? 0.f : 1.f;
        dd = x.w - tt; wgt = ((nib & 8u) ? 0.f : wb.w) + 0.001f; sw += wgt * dd * dd;
        px = 1.f / (1.f + __expf(-x.w)); sp += px; st += tt; spt += px * tt;
    }

    float vals[4] = {sw, sp, st, spt};
    #pragma unroll
    for (int q = 0; q < 4; ++q) {
        float s = vals[q];
        #pragma unroll
        for (int o = 16; o > 0; o >>= 1)
            s += __shfl_down_sync(0xffffffffu, s, o);
        if ((threadIdx.x & 31) == 0) red[q][threadIdx.x >> 5] = s;
    }
    __syncthreads();
    if (threadIdx.x < 8) {
        #pragma unroll
        for (int q = 0; q < 4; ++q) {
            float s = red[q][threadIdx.x];
            #pragma unroll
            for (int o = 4; o > 0; o >>= 1)
                s += __shfl_down_sync(0xffu, s, o);
            if (threadIdx.x == 0)
                atomicAdd(&g_acc[q], (double)s);
        }
    }
    __syncthreads();

    if (threadIdx.x == 0) {
        __threadfence();
        unsigned n = atomicAdd(&g_done, 1u);
        s_last = (n == MAIN_TOTAL - 1);
    }
    __syncthreads();
    if (s_last && threadIdx.x == 0) {
        double wmse = g_acc[0] / (double)NPIX;
        double P = g_acc[1], T = g_acc[2], I = g_acc[3];
        double dice = 1.0 - (2.0 * I + 1e-6) / (P + T + 1e-6);
        if (out_size >= 1) out[0] = (float)(0.6 * wmse);
        if (out_size >= 2) out[1] = (float)(1.0 * dice);
    }
}

// ---------------- launch ----------------
extern "C" void kernel_launch(void* const* d_in, const int* in_sizes, int n_in,
                              void* d_out, int out_size) {
    const float* inputs  = (const float*)d_in[0];
    const float* targets = (const float*)d_in[1];
    float* out = (float*)d_out;

    dim3 gv(W_ / 32, B_);
    k_vert<<<gv, 512>>>(targets);
    k_row<<<B_ * H_ / 2, 1024>>>();
    dim3 g3(MAIN_BLOCKS_X, B_);
    k_main<<<g3, 256>>>((const float4*)inputs, out, out_size);
}

// round 5
// speedup vs baseline: 1.0516x; 1.0161x over previous
#include <cuda_runtime.h>
#include <math.h>

#define B_    16
#define H_    512
#define W_    512
#define NPIX  (B_ * H_ * W_)
#define BIGF  100000000.0f
#define SENTI (1 << 28)
#define GRID  296          // 2 CTAs per SM on 148 SMs; guaranteed co-resident
#define THREADS 256
#define MAIN_BLOCKS 256    // blocks participating in phase 3 (16 per batch)

// ---------------- scratch (device globals; no allocation) ----------------
__device__ unsigned short g_d[NPIX];            // vertical distance (0..511; >511 => BIG)
__device__ unsigned int   g_zmask[NPIX / 32];   // row-major zero bitmask of targets
__device__ float  g_rowsf[B_ * W_];             // f (squared) at h==b rows
__device__ int    g_maxf[B_];                   // per-batch max f (float bits)
__device__ double g_acc[4];                     // [wmse, sum_p, sum_t, sum_pt]
__device__ unsigned int g_done;
__device__ unsigned int bar_count;
__device__ volatile unsigned int bar_gen;

// -------- sense-reversal grid barrier (all GRID blocks co-resident) --------
__device__ __forceinline__ void grid_barrier() {
    __syncthreads();
    if (threadIdx.x == 0) {
        unsigned gen = bar_gen;
        __threadfence();
        if (atomicAdd(&bar_count, 1u) == GRID - 1u) {
            bar_count = 0u;
            __threadfence();
            bar_gen = gen + 1u;
        } else {
            while (bar_gen == gen) { __nanosleep(64); }
        }
        __threadfence();
    }
    __syncthreads();
}

__global__ void __launch_bounds__(THREADS, 2)
k_fused(const float* __restrict__ t, const float4* __restrict__ in4,
        float* __restrict__ out, int out_size) {
    __shared__ int   s_first[16][32];
    __shared__ int   s_last[16][32];
    __shared__ float srow[8][W_];        // phase 2: one row per warp
    __shared__ float s_wb[W_];           // phase 3 weight-base
    __shared__ float red[4][8];

    const int bid  = blockIdx.x;
    const int tid  = threadIdx.x;
    const int w    = tid >> 5;
    const int lane = tid & 31;

    // -------- init accumulators (block 0) --------
    if (bid == 0) {
        if (tid < B_) g_maxf[tid] = 0;
        if (tid < 4)  g_acc[tid]  = 0.0;
        if (tid == 31) g_done = 0u;
    }

    // ================= PHASE 1: vertical distances + zero bitmask =================
    if (bid < 256) {
        const int b  = bid >> 4;
        const int cg = bid & 15;
        const int col = cg * 32 + lane;
        const float* tb = t + (size_t)b * H_ * W_;

        unsigned cm[2];
        #pragma unroll
        for (int sub = 0; sub < 2; ++sub) {
            const int r0 = w * 64 + sub * 32;
            unsigned colmask = 0u, myrow = 0u;
            #pragma unroll
            for (int i = 0; i < 32; ++i) {
                float z = tb[(size_t)(r0 + i) * W_ + col];
                unsigned m = __ballot_sync(0xffffffffu, z == 0.0f);
                if (lane == i) myrow = m;
                colmask |= ((m >> lane) & 1u) << i;
            }
            g_zmask[((size_t)b * H_ + r0 + lane) * (W_ / 32) + cg] = myrow;
            const int c = 2 * w + sub;
            s_last[c][lane]  = colmask ? (r0 + 31 - __clz(colmask)) : -SENTI;
            s_first[c][lane] = colmask ? (r0 + __ffs(colmask) - 1)  :  SENTI;
            cm[sub] = colmask;
        }
        __syncthreads();

        unsigned short* gbase = g_d + (size_t)b * H_ * W_ + col;
        for (int sub = 0; sub < 2; ++sub) {
            const int r0 = w * 64 + sub * 32;
            const int c  = 2 * w + sub;
            int lastAbove = -SENTI, nextBelow = SENTI;
            #pragma unroll
            for (int k = 0; k < 16; ++k) {
                int ll = s_last[k][lane];
                int ff = s_first[k][lane];
                if (k < c) lastAbove = max(lastAbove, ll);
                if (k > c) nextBelow = min(nextBelow, ff);
            }
            const unsigned colmask = cm[sub];
            int dn[32];
            int d = nextBelow - (r0 + 32);
            #pragma unroll
            for (int i = 31; i >= 0; --i) {
                d = ((colmask >> i) & 1u) ? 0 : d + 1;
                dn[i] = d;
            }
            int du = (r0 - 1) - lastAbove;
            #pragma unroll
            for (int i = 0; i < 32; ++i) {
                du = ((colmask >> i) & 1u) ? 0 : du + 1;
                int dm = min(du, dn[i]);
                gbase[(size_t)(r0 + i) * W_] = (unsigned short)min(dm, 0x7FFF);
            }
        }
    }

    grid_barrier();

    // ================= PHASE 2: row transform (warp per row) =================
    {
        float* sr = srow[w];
        for (int bh = bid * 8 + w; bh < B_ * H_; bh += GRID * 8) {
            const unsigned short* grow = g_d + (size_t)bh * W_;
            #pragma unroll
            for (int j = 0; j < 16; ++j) {
                int y = lane + 32 * j;
                int dm = grow[y];
                sr[y] = (dm > 511) ? BIGF : (float)(dm * dm);
            }
            __syncwarp();

            const int b = bh >> 9;
            const int h = bh & 511;
            float m = 0.0f;
            for (int j = 0; j < 16; ++j) {
                int y = lane + 32 * j;
                float best = sr[y];
                for (int r = 1; r < W_; ++r) {
                    float r2 = (float)(r * r);
                    if (r2 >= best) break;          // exact early termination
                    int jl = y - r, jr = y + r;
                    if (jl >= 0)  best = fminf(best, sr[jl] + r2);
                    if (jr < W_)  best = fminf(best, sr[jr] + r2);
                }
                if (h == b) g_rowsf[b * W_ + y] = best;
                m = fmaxf(m, best);
            }
            #pragma unroll
            for (int o = 16; o > 0; o >>= 1)
                m = fmaxf(m, __shfl_down_sync(0xffffffffu, m, o));
            if (lane == 0)
                atomicMax(&g_maxf[b], __float_as_int(m));
            __syncwarp();
        }
    }

    grid_barrier();

    // ================= PHASE 3: fused weighted MSE + dice =================
    if (bid < MAIN_BLOCKS) {
        const int b  = bid >> 4;
        const int xc = bid & 15;
        const float v = sqrtf(__int_as_float(g_maxf[b]));
        {
            s_wb[tid]       = v - sqrtf(g_rowsf[b * W_ + tid]);
            s_wb[tid + 256] = v - sqrtf(g_rowsf[b * W_ + tid + 256]);
        }
        __syncthreads();

        const size_t base4 = (size_t)b * (H_ * W_ / 4);
        const size_t basew = (size_t)b * (H_ * W_ / 32);
        const float4* wb4 = (const float4*)s_wb;

        float sw = 0.f, sp = 0.f, st = 0.f, spt = 0.f;
        #pragma unroll
        for (int k = 0; k < 16; ++k) {
            int fi = xc * 4096 + k * 256 + tid;
            float4 x = in4[base4 + fi];
            unsigned nib = (g_zmask[basew + (fi >> 3)] >> ((fi & 7) * 4)) & 0xFu;
            float4 wb = wb4[fi & 127];

            float px, wgt, dd, tt;
            tt = (nib & 1u) ? 0.f : 1.f;
            dd = x.x - tt; wgt = ((nib & 1u) ? 0.f : wb.x) + 0.001f; sw += wgt * dd * dd;
            px = 1.f / (1.f + __expf(-x.x)); sp += px; st += tt; spt += px * tt;
            tt = (nib & 2u) ? 0.f : 1.f;
            dd = x.y - tt; wgt = ((nib & 2u) ? 0.f : wb.y) + 0.001f; sw += wgt * dd * dd;
            px = 1.f / (1.f + __expf(-x.y)); sp += px; st += tt; spt += px * tt;
            tt = (nib & 4u) ? 0.f : 1.f;
            dd = x.z - tt; wgt = ((nib & 4u) ? 0.f : wb.z) + 0.001f; sw += wgt * dd * dd;
            px = 1.f / (1.f + __expf(-x.z)); sp += px; st += tt; spt += px * tt;
            tt = (nib & 8u) ? 0.f : 1.f;
            dd = x.w - tt; wgt = ((nib & 8u) ? 0.f : wb.w) + 0.001f; sw += wgt * dd * dd;
            px = 1.f / (1.f + __expf(-x.w)); sp += px; st += tt; spt += px * tt;
        }

        float vals[4] = {sw, sp, st, spt};
        #pragma unroll
        for (int q = 0; q < 4; ++q) {
            float s = vals[q];
            #pragma unroll
            for (int o = 16; o > 0; o >>= 1)
                s += __shfl_down_sync(0xffffffffu, s, o);
            if (lane == 0) red[q][w] = s;
        }
        __syncthreads();
        if (tid < 8) {
            #pragma unroll
            for (int q = 0; q < 4; ++q) {
                float s = red[q][tid];
                #pragma unroll
                for (int o = 4; o > 0; o >>= 1)
                    s += __shfl_down_sync(0xffu, s, o);
                if (tid == 0)
                    atomicAdd(&g_acc[q], (double)s);
            }
        }
        __syncthreads();

        // completion counter: last participating block finalizes
        __shared__ bool s_lastb;
        if (tid == 0) {
            __threadfence();
            unsigned n = atomicAdd(&g_done, 1u);
            s_lastb = (n == MAIN_BLOCKS - 1u);
        }
        __syncthreads();
        if (s_lastb && tid == 0) {
            double wmse = g_acc[0] / (double)NPIX;
            double P = g_acc[1], T = g_acc[2], I = g_acc[3];
            double dice = 1.0 - (2.0 * I + 1e-6) / (P + T + 1e-6);
            if (out_size >= 1) out[0] = (float)(0.6 * wmse);
            if (out_size >= 2) out[1] = (float)(1.0 * dice);
        }
    }
}

// ---------------- launch ----------------
extern "C" void kernel_launch(void* const* d_in, const int* in_sizes, int n_in,
                              void* d_out, int out_size) {
    const float* inputs  = (const float*)d_in[0];
    const float* targets = (const float*)d_in[1];
    float* out = (float*)d_out;

    k_fused<<<GRID, THREADS>>>(targets, (const float4*)inputs, out, out_size);
}

// round 6
// speedup vs baseline: 1.2538x; 1.1923x over previous
#include <cuda_runtime.h>
#include <math.h>

#define B_    16
#define H_    512
#define W_    512
#define NPIX  (B_ * H_ * W_)
#define BIGF  100000000.0f
#define SENTI (1 << 28)
#define MAIN_BX 64
#define MAIN_TOTAL (MAIN_BX * B_)

// ---------------- scratch (device globals; no allocation) ----------------
__device__ unsigned short g_d[NPIX];            // vertical distance (0..511; >511 => BIG)
__device__ unsigned int   g_zmask[NPIX / 32];   // row-major zero bitmask of targets
__device__ float  g_rowsf[B_ * W_];             // f (squared) at h==b rows
__device__ int    g_maxf[B_];                   // per-batch max f (float bits)
__device__ double g_acc[4];                     // [wmse, sum_p, sum_t, sum_pt]
__device__ unsigned int g_done;

// ================= K1: vertical distances + zero bitmask =================
// grid (16,16): 32-col group x batch. Block 512 = 16 warps; warp w: rows [32w,32w+32).
__global__ void __launch_bounds__(512, 2)
k_vert(const float* __restrict__ t) {
    __shared__ int s_first[16][32];
    __shared__ int s_last[16][32];
    __shared__ unsigned short sdn[32][512];   // [row-within-chunk][tid] backward distances

    const int lane = threadIdx.x & 31;
    const int w    = threadIdx.x >> 5;
    const int cg   = blockIdx.x;
    const int b    = blockIdx.y;
    const int col  = cg * 32 + lane;
    const int r0   = w * 32;

    if (blockIdx.x == 0 && blockIdx.y == 0) {
        if (threadIdx.x < B_) g_maxf[threadIdx.x] = 0;
        if (threadIdx.x < 4)  g_acc[threadIdx.x]  = 0.0;
        if (threadIdx.x == 31) g_done = 0u;
    }

    const float* tb = t + (size_t)b * H_ * W_;

    // load 32 rows; ballot -> row-major zero masks + column mask (transpose for free)
    unsigned colmask = 0u, myrow = 0u;
    #pragma unroll
    for (int i = 0; i < 32; ++i) {
        float z = tb[(size_t)(r0 + i) * W_ + col];
        unsigned m = __ballot_sync(0xffffffffu, z == 0.0f);
        if (lane == i) myrow = m;
        colmask |= ((m >> lane) & 1u) << i;
    }
    g_zmask[((size_t)b * H_ + r0 + lane) * (W_ / 32) + cg] = myrow;

    s_last[w][lane]  = colmask ? (r0 + 31 - __clz(colmask)) : -SENTI;
    s_first[w][lane] = colmask ? (r0 + __ffs(colmask) - 1)  :  SENTI;
    __syncthreads();

    int lastAbove = -SENTI, nextBelow = SENTI;
    #pragma unroll
    for (int k = 0; k < 16; ++k) {
        int ll = s_last[k][lane];
        int ff = s_first[k][lane];
        if (k < w) lastAbove = max(lastAbove, ll);
        if (k > w) nextBelow = min(nextBelow, ff);
    }

    // backward pass -> shared
    {
        int d = min(nextBelow - (r0 + 32), 0x7FFE);
        #pragma unroll
        for (int i = 31; i >= 0; --i) {
            d = ((colmask >> i) & 1u) ? 0 : d + 1;
            sdn[i][threadIdx.x] = (unsigned short)d;
        }
    }
    // forward pass + emit
    unsigned short* gbase = g_d + (size_t)b * H_ * W_ + col;
    {
        int du = min((r0 - 1) - lastAbove, 0x7FFE);
        #pragma unroll
        for (int i = 0; i < 32; ++i) {
            du = ((colmask >> i) & 1u) ? 0 : du + 1;
            int dm = min(du, (int)sdn[i][threadIdx.x]);
            gbase[(size_t)(r0 + i) * W_] = (unsigned short)min(dm, 0x7FFF);
        }
    }
}

// ================= K2: row transform (warp per row) =================
// grid 1024, block 256 (8 warps -> 8 rows per block).
__global__ void __launch_bounds__(256)
k_row() {
    __shared__ float srow[8][W_];

    const int w    = threadIdx.x >> 5;
    const int lane = threadIdx.x & 31;
    const int bh   = blockIdx.x * 8 + w;       // 0..8191
    const int b    = bh >> 9;
    const int h    = bh & 511;

    float* sr = srow[w];
    const unsigned short* grow = g_d + (size_t)bh * W_;
    #pragma unroll
    for (int j = 0; j < 16; ++j) {
        int y = lane + 32 * j;
        int dm = grow[y];
        sr[y] = (dm > 511) ? BIGF : (float)(dm * dm);
    }
    __syncwarp();

    float m = 0.0f;
    #pragma unroll 1
    for (int j = 0; j < 16; ++j) {
        int y = lane + 32 * j;
        float best = sr[y];
        for (int r = 1; r < W_; ++r) {
            float r2 = (float)(r * r);
            if (r2 >= best) break;             // exact early termination
            int jl = y - r, jr = y + r;
            if (jl >= 0)  best = fminf(best, sr[jl] + r2);
            if (jr < W_)  best = fminf(best, sr[jr] + r2);
        }
        if (h == b) g_rowsf[b * W_ + y] = best;
        m = fmaxf(m, best);
    }
    #pragma unroll
    for (int o = 16; o > 0; o >>= 1)
        m = fmaxf(m, __shfl_down_sync(0xffffffffu, m, o));
    if (lane == 0)
        atomicMax(&g_maxf[b], __float_as_int(m));
}

// ================= K3: fused weighted MSE + dice + finalize =================
// grid (MAIN_BX, B_), block 256; 4 float4 per thread. Targets from bitmask.
__global__ void __launch_bounds__(256)
k_main(const float4* __restrict__ in4, float* __restrict__ out, int out_size) {
    __shared__ float s_wb[W_];
    __shared__ float red[4][8];
    __shared__ bool  s_lastb;

    const int tid = threadIdx.x;
    const int b   = blockIdx.y;
    const float v = sqrtf(__int_as_float(g_maxf[b]));
    {
        s_wb[tid]       = v - sqrtf(g_rowsf[b * W_ + tid]);
        s_wb[tid + 256] = v - sqrtf(g_rowsf[b * W_ + tid + 256]);
    }
    __syncthreads();

    const size_t base4 = (size_t)b * (H_ * W_ / 4);
    const size_t basew = (size_t)b * (H_ * W_ / 32);
    const int q0 = blockIdx.x * 256 + tid;
    const float4* wb4 = (const float4*)s_wb;

    float sw = 0.f, sp = 0.f, st = 0.f, spt = 0.f;
    #pragma unroll
    for (int k = 0; k < 4; ++k) {
        int fi = q0 + k * (MAIN_BX * 256);
        float4 x = in4[base4 + fi];
        unsigned nib = (g_zmask[basew + (fi >> 3)] >> ((fi & 7) * 4)) & 0xFu;
        float4 wb = wb4[fi & 127];

        float px, wgt, dd, tt;
        tt = (nib & 1u) ? 0.f : 1.f;
        dd = x.x - tt; wgt = ((nib & 1u) ? 0.f : wb.x) + 0.001f; sw += wgt * dd * dd;
        px = 1.f / (1.f + __expf(-x.x)); sp += px; st += tt; spt += px * tt;
        tt = (nib & 2u) ? 0.f : 1.f;
        dd = x.y - tt; wgt = ((nib & 2u) ? 0.f : wb.y) + 0.001f; sw += wgt * dd * dd;
        px = 1.f / (1.f + __expf(-x.y)); sp += px; st += tt; spt += px * tt;
        tt = (nib & 4u) ? 0.f : 1.f;
        dd = x.z - tt; wgt = ((nib & 4u) ? 0.f : wb.z) + 0.001f; sw += wgt * dd * dd;
        px = 1.f / (1.f + __expf(-x.z)); sp += px; st += tt; spt += px * tt;
        tt = (nib & 8u) ? 0.f : 1.f;
        dd = x.w - tt; wgt = ((nib & 8u) ? 0.f : wb.w) + 0.001f; sw += wgt * dd * dd;
        px = 1.f / (1.f + __expf(-x.w)); sp += px; st += tt; spt += px * tt;
    }

    float vals[4] = {sw, sp, st, spt};
    #pragma unroll
    for (int q = 0; q < 4; ++q) {
        float s = vals[q];
        #pragma unroll
        for (int o = 16; o > 0; o >>= 1)
            s += __shfl_down_sync(0xffffffffu, s, o);
        if ((tid & 31) == 0) red[q][tid >> 5] = s;
    }
    __syncthreads();
    if (tid < 8) {
        #pragma unroll
        for (int q = 0; q < 4; ++q) {
            float s = red[q][tid];
            #pragma unroll
            for (int o = 4; o > 0; o >>= 1)
                s += __shfl_down_sync(0xffu, s, o);
            if (tid == 0)
                atomicAdd(&g_acc[q], (double)s);
        }
    }
    __syncthreads();

    if (tid == 0) {
        __threadfence();
        unsigned n = atomicAdd(&g_done, 1u);
        s_lastb = (n == MAIN_TOTAL - 1u);
    }
    __syncthreads();
    if (s_lastb && tid == 0) {
        double wmse = g_acc[0] / (double)NPIX;
        double P = g_acc[1], T = g_acc[2], I = g_acc[3];
        double dice = 1.0 - (2.0 * I + 1e-6) / (P + T + 1e-6);
        if (out_size >= 1) out[0] = (float)(0.6 * wmse);
        if (out_size >= 2) out[1] = (float)(1.0 * dice);
    }
}

// ---------------- launch ----------------
extern "C" void kernel_launch(void* const* d_in, const int* in_sizes, int n_in,
                              void* d_out, int out_size) {
    const float* inputs  = (const float*)d_in[0];
    const float* targets = (const float*)d_in[1];
    float* out = (float*)d_out;

    dim3 gv(16, B_);
    k_vert<<<gv, 512>>>(targets);
    k_row<<<B_ * H_ / 8, 256>>>();
    dim3 g3(MAIN_BX, B_);
    k_main<<<g3, 256>>>((const float4*)inputs, out, out_size);
}